// round 17
// baseline (speedup 1.0000x reference)
#include <cuda_runtime.h>
#include <math.h>

#define B_   16
#define T_   512
#define F_   17
#define K_   20
#define FEAT (F_*K_)        // 340
#define FL   30
#define NFR  (T_ - FL + 1)  // 483
#define GF   7              // frames per corr CTA (483 = 69*7 exactly)
#define NGRP (NFR / GF)     // 69
#define ROWS_ST (FL + GF - 1)  // 36 staged rows
#define TB   30
#define NTBLK ((T_ + TB - 1) / TB)   // 18
#define EPSF 1e-12f

__device__ float g_bufA[2 * B_ * T_ * F_ * K_];
__device__ float g_bufB[2 * B_ * T_ * F_ * K_];

__constant__ __align__(16) float CW0[9 * 1  * K_];
__constant__ __align__(16) float CW1[9 * K_ * K_];
__constant__ __align__(16) float CW2[9 * K_ * K_];
__constant__ float CB0[K_];
__constant__ float CB1[K_];
__constant__ float CB2[K_];

// ---------------------------------------------------------------------------
// Layer 0 conv (CIN=1). Proven structure; float4 stores.
// ---------------------------------------------------------------------------
__global__ void __launch_bounds__(256) conv1_kernel(
    const float* __restrict__ in0, const float* __restrict__ in1)
{
    extern __shared__ float tile[];   // (TB+2)*(F_+2)

    const int tid = threadIdx.x;
    const int t0  = blockIdx.x * TB;
    const int bb  = blockIdx.y;

    const float* src = (bb < B_) ? (in0 + (size_t)bb * T_ * F_)
                                 : (in1 + (size_t)(bb - B_) * T_ * F_);
    float* dst = g_bufA;

    const int tileN = (TB + 2) * (F_ + 2);
    for (int i = tid; i < tileN; i += 256) {
        int ff = i % (F_ + 2);
        int tt = i / (F_ + 2);
        int t = t0 - 1 + tt;
        int f = ff - 1;
        float v = 0.f;
        if (t >= 0 && t < T_ && f >= 0 && f < F_)
            v = src[(size_t)t * F_ + f];
        tile[i] = v;
    }
    __syncthreads();

    float acc0[K_], acc1[K_];
#pragma unroll
    for (int k = 0; k < K_; k++) { acc0[k] = CB0[k]; acc1[k] = CB0[k]; }

    const bool ok1 = (tid + 256 < TB * F_);
    const int pos0 = tid;
    const int pos1 = ok1 ? (tid + 256) : 0;
    const int lt0 = pos0 / F_, lf0 = pos0 % F_;
    const int lt1 = pos1 / F_, lf1 = pos1 % F_;

#pragma unroll
    for (int dt = 0; dt < 3; dt++) {
#pragma unroll
        for (int df = 0; df < 3; df++) {
            const int wbase = (dt * 3 + df) * K_;
            float i0 = tile[(lt0 + dt) * (F_ + 2) + lf0 + df];
            float i1 = tile[(lt1 + dt) * (F_ + 2) + lf1 + df];
#pragma unroll
            for (int k = 0; k < K_; k++) {
                float wv = CW0[wbase + k];
                acc0[k] = fmaf(i0, wv, acc0[k]);
                acc1[k] = fmaf(i1, wv, acc1[k]);
            }
        }
    }

    if ((t0 + lt0) < T_) {
        float4* o4 = reinterpret_cast<float4*>(
            dst + (((size_t)bb * T_ + t0 + lt0) * F_ + lf0) * K_);
#pragma unroll
        for (int q = 0; q < 5; q++) {
            float4 r;
            r.x = fmaxf(acc0[4*q+0], 0.f);
            r.y = fmaxf(acc0[4*q+1], 0.f);
            r.z = fmaxf(acc0[4*q+2], 0.f);
            r.w = fmaxf(acc0[4*q+3], 0.f);
            o4[q] = r;
        }
    }
    if (ok1 && (t0 + lt1) < T_) {
        float4* o4 = reinterpret_cast<float4*>(
            dst + (((size_t)bb * T_ + t0 + lt1) * F_ + lf1) * K_);
#pragma unroll
        for (int q = 0; q < 5; q++) {
            float4 r;
            r.x = fmaxf(acc1[4*q+0], 0.f);
            r.y = fmaxf(acc1[4*q+1], 0.f);
            r.z = fmaxf(acc1[4*q+2], 0.f);
            r.w = fmaxf(acc1[4*q+3], 0.f);
            o4[q] = r;
        }
    }
}

// ---------------------------------------------------------------------------
// Layers 1/2 conv (CIN=20) — R17: taps FULLY UNROLLED on top of the R16
// interchange. All LDS/LDC are base+immediate, zero mainloop control.
// Body ~8.5K instrs (~135KB SASS): I$-L2 plateau ~+5%, low-grid throttle
// vanishes at grid>=148 (grid=576).
// ---------------------------------------------------------------------------
template<int SRC, int DST, int LAYER>
__global__ void __launch_bounds__(256) conv20_kernel()
{
    constexpr int CIN  = K_;
    constexpr int CINP = K_ + 1;   // 21

    extern __shared__ float tile[];   // (TB+2)*(F_+2)*CINP

    const int tid = threadIdx.x;
    const int t0  = blockIdx.x * TB;
    const int bb  = blockIdx.y;

    const float* src = ((SRC == 0) ? g_bufA : g_bufB) + (size_t)bb * T_ * F_ * CIN;
    float* dst = ((DST == 0) ? g_bufA : g_bufB);

    const int tileN = (TB + 2) * (F_ + 2) * CIN;
    for (int i = tid; i < tileN; i += 256) {
        int cin  = i % CIN;
        int rest = i / CIN;
        int ff   = rest % (F_ + 2);
        int tt   = rest / (F_ + 2);
        int t = t0 - 1 + tt;
        int f = ff - 1;
        float v = 0.f;
        if (t >= 0 && t < T_ && f >= 0 && f < F_)
            v = src[((size_t)t * F_ + f) * CIN + cin];
        tile[(tt * (F_ + 2) + ff) * CINP + cin] = v;
    }
    __syncthreads();

    float acc0[K_], acc1[K_];
#pragma unroll
    for (int k = 0; k < K_; k++) {
        float bk = (LAYER == 1) ? CB1[k] : CB2[k];
        acc0[k] = bk; acc1[k] = bk;
    }

    const bool ok0 = (tid < TB * F_);
    const bool ok1 = (tid + 256 < TB * F_);
    const int pos0 = ok0 ? tid : 0;
    const int pos1 = ok1 ? (tid + 256) : 0;
    const int b0c = ((pos0 / F_) * (F_ + 2) + (pos0 % F_)) * CINP;
    const int b1c = ((pos1 / F_) * (F_ + 2) + (pos1 % F_)) * CINP;

    const float* cw = (LAYER == 1) ? CW1 : CW2;
    const float* tb0 = tile + b0c;
    const float* tb1 = tile + b1c;

#pragma unroll
    for (int dt = 0; dt < 3; dt++) {
#pragma unroll
        for (int df = 0; df < 3; df++) {
            const int toff = (dt * (F_ + 2) + df) * CINP;          // compile-time
            const float* wp = cw + (dt * 3 + df) * (CIN * K_);     // base + imm
#pragma unroll
            for (int cin = 0; cin < CIN; cin++) {
                float i0 = tb0[toff + cin];
                float i1 = tb1[toff + cin];
#pragma unroll
                for (int q = 0; q < 5; q++) {
                    float4 wv = reinterpret_cast<const float4*>(wp + cin * K_)[q];
                    acc0[4*q+0] = fmaf(i0, wv.x, acc0[4*q+0]);
                    acc0[4*q+1] = fmaf(i0, wv.y, acc0[4*q+1]);
                    acc0[4*q+2] = fmaf(i0, wv.z, acc0[4*q+2]);
                    acc0[4*q+3] = fmaf(i0, wv.w, acc0[4*q+3]);
                    acc1[4*q+0] = fmaf(i1, wv.x, acc1[4*q+0]);
                    acc1[4*q+1] = fmaf(i1, wv.y, acc1[4*q+1]);
                    acc1[4*q+2] = fmaf(i1, wv.z, acc1[4*q+2]);
                    acc1[4*q+3] = fmaf(i1, wv.w, acc1[4*q+3]);
                }
            }
        }
    }

    if (ok0 && (t0 + pos0 / F_) < T_) {
        int t = t0 + pos0 / F_;
        float4* o4 = reinterpret_cast<float4*>(
            dst + (((size_t)bb * T_ + t) * F_ + pos0 % F_) * K_);
#pragma unroll
        for (int q = 0; q < 5; q++) {
            float4 r;
            r.x = fmaxf(acc0[4*q+0], 0.f);
            r.y = fmaxf(acc0[4*q+1], 0.f);
            r.z = fmaxf(acc0[4*q+2], 0.f);
            r.w = fmaxf(acc0[4*q+3], 0.f);
            o4[q] = r;
        }
    }
    if (ok1 && (t0 + pos1 / F_) < T_) {
        int t = t0 + pos1 / F_;
        float4* o4 = reinterpret_cast<float4*>(
            dst + (((size_t)bb * T_ + t) * F_ + pos1 % F_) * K_);
#pragma unroll
        for (int q = 0; q < 5; q++) {
            float4 r;
            r.x = fmaxf(acc1[4*q+0], 0.f);
            r.y = fmaxf(acc1[4*q+1], 0.f);
            r.z = fmaxf(acc1[4*q+2], 0.f);
            r.w = fmaxf(acc1[4*q+3], 0.f);
            o4[q] = r;
        }
    }
}

// ---------------------------------------------------------------------------
// Grouped corr — R17: 768 threads/CTA, 2 CTAs/SM -> 48 warps/SM (was 32;
// kernel is MIO-latency limited). regs capped 42 by launch_bounds(768,2)
// (1536*42 = 64.5K regs/SM, fits). Stats single-pass (680 < 768 threads).
// Phase B: 24 warps stride rows by 24. fp32 throughout, fresh per-frame
// one-pass stats (the only numerically validated form).
// ---------------------------------------------------------------------------
__global__ void __launch_bounds__(768, 2) corr_kernel(float* __restrict__ out)
{
    extern __shared__ float sm[];
    float*  rawS = sm;                       // 36*340 fp32
    float*  rawX = sm + ROWS_ST * FEAT;      // 36*340 fp32
    float4* coef = reinterpret_cast<float4*>(sm + 2 * ROWS_ST * FEAT); // 340 float4
    __shared__ float red[24];

    const int grp = blockIdx.x;   // 0..68
    const int b   = blockIdx.y;   // 0..15
    const int tid = threadIdx.x;
    const int fr0 = grp * GF;

    const float* S = g_bufA + ((size_t)b * T_ + fr0) * FEAT;
    const float* X = g_bufA + ((size_t)(b + B_) * T_ + fr0) * FEAT;

    {
        const int n4 = ROWS_ST * FEAT / 4;   // 3060
        const float4* S4 = reinterpret_cast<const float4*>(S);
        const float4* X4 = reinterpret_cast<const float4*>(X);
        float4* rS4 = reinterpret_cast<float4*>(rawS);
        float4* rX4 = reinterpret_cast<float4*>(rawX);
        for (int i = tid; i < n4; i += 768) { rS4[i] = S4[i]; rX4[i] = X4[i]; }
    }
    __syncthreads();

    const int warp = tid >> 5, lane = tid & 31;
    float acc = 0.f;

    for (int j = 0; j < GF; j++) {
        if (j > 0) __syncthreads();   // prior Phase B done before coef overwrite

        // Fresh one-pass column stats for frame j (rows j..j+29) -> coef.
        if (tid < 2 * FEAT) {
            const bool isS = (tid < FEAT);
            const int col = isS ? tid : tid - FEAT;
            const float* base = isS ? rawS : rawX;
            float s = 0.f, s2 = 0.f;
#pragma unroll
            for (int t = 0; t < FL; t++) {
                float r = base[(j + t) * FEAT + col];
                s += r; s2 = fmaf(r, r, s2);
            }
            float mu  = s * (1.0f / FL);
            float var = fmaxf(s2 - (float)FL * mu * mu, 0.f);
            float inv = 1.f / (sqrtf(var) + EPSF);
            if (isS) { coef[col].x = mu; coef[col].y = inv; }
            else     { coef[col].z = mu; coef[col].w = inv; }
        }
        __syncthreads();

        // Phase B: 24 warps stride rows by 24 (rows w and w+24 for w<6).
        for (int t = warp; t < FL; t += 24) {
            const float* rS = rawS + (j + t) * FEAT;
            const float* rX = rawX + (j + t) * FEAT;
            float aU = 0.f, aV = 0.f, a2U = 0.f, a2V = 0.f, aUV = 0.f;
#pragma unroll
            for (int it = 0; it < 11; it++) {
                int c = it * 32 + lane;
                if (c < FEAT) {
                    float4 cf = coef[c];
                    float u = (rS[c] - cf.x) * cf.y;
                    float v = (rX[c] - cf.z) * cf.w;
                    aU += u; aV += v;
                    a2U = fmaf(u, u, a2U);
                    a2V = fmaf(v, v, a2V);
                    aUV = fmaf(u, v, aUV);
                }
            }
#pragma unroll
            for (int o = 16; o > 0; o >>= 1) {
                aU  += __shfl_down_sync(0xffffffffu, aU,  o);
                aV  += __shfl_down_sync(0xffffffffu, aV,  o);
                a2U += __shfl_down_sync(0xffffffffu, a2U, o);
                a2V += __shfl_down_sync(0xffffffffu, a2V, o);
                aUV += __shfl_down_sync(0xffffffffu, aUV, o);
            }
            if (lane == 0) {
                float muU = aU * (1.0f / FEAT), muV = aV * (1.0f / FEAT);
                float sgU = sqrtf(fmaxf(a2U - (float)FEAT * muU * muU, 0.f));
                float sgV = sqrtf(fmaxf(a2V - (float)FEAT * muV * muV, 0.f));
                float dot = aUV - (float)FEAT * muU * muV;
                acc += dot / ((sgU + EPSF) * (sgV + EPSF));
            }
        }
    }

    if (lane == 0) red[warp] = acc;
    __syncthreads();
    if (tid == 0) {
        float tot = 0.f;
#pragma unroll
        for (int i = 0; i < 24; i++) tot += red[i];
        atomicAdd(&out[b], tot * (1.0f / ((float)FL * (float)NFR)));
    }
}

__global__ void zero_out(float* out, int n)
{
    int i = blockIdx.x * blockDim.x + threadIdx.x;
    if (i < n) out[i] = 0.f;
}

extern "C" void kernel_launch(void* const* d_in, const int* in_sizes, int n_in,
                              void* d_out, int out_size)
{
    const float* s  = (const float*)d_in[0];
    const float* x  = (const float*)d_in[1];
    const float* w0 = (const float*)d_in[2];
    const float* b0 = (const float*)d_in[3];
    const float* w1 = (const float*)d_in[4];
    const float* b1 = (const float*)d_in[5];
    const float* w2 = (const float*)d_in[6];
    const float* b2 = (const float*)d_in[7];
    float* out = (float*)d_out;

    cudaMemcpyToSymbolAsync(CW0, w0, 9 * 1  * K_ * sizeof(float), 0, cudaMemcpyDeviceToDevice, 0);
    cudaMemcpyToSymbolAsync(CB0, b0, K_ * sizeof(float),          0, cudaMemcpyDeviceToDevice, 0);
    cudaMemcpyToSymbolAsync(CW1, w1, 9 * K_ * K_ * sizeof(float), 0, cudaMemcpyDeviceToDevice, 0);
    cudaMemcpyToSymbolAsync(CB1, b1, K_ * sizeof(float),          0, cudaMemcpyDeviceToDevice, 0);
    cudaMemcpyToSymbolAsync(CW2, w2, 9 * K_ * K_ * sizeof(float), 0, cudaMemcpyDeviceToDevice, 0);
    cudaMemcpyToSymbolAsync(CB2, b2, K_ * sizeof(float),          0, cudaMemcpyDeviceToDevice, 0);

    zero_out<<<1, 32>>>(out, out_size);

    const int smem1  = (TB + 2) * (F_ + 2) * 1  * (int)sizeof(float);  //  2432 B
    const int smem20 = (TB + 2) * (F_ + 2) * 21 * (int)sizeof(float);  // 51072 B
    const int smemC  = (2 * ROWS_ST * FEAT) * (int)sizeof(float)
                     + FEAT * (int)sizeof(float4);                     // 103360 B

    cudaFuncSetAttribute(conv20_kernel<0, 1, 1>,
                         cudaFuncAttributeMaxDynamicSharedMemorySize, smem20);
    cudaFuncSetAttribute(conv20_kernel<1, 0, 2>,
                         cudaFuncAttributeMaxDynamicSharedMemorySize, smem20);
    cudaFuncSetAttribute(corr_kernel,
                         cudaFuncAttributeMaxDynamicSharedMemorySize, smemC);

    dim3 cgrid(NTBLK, 2 * B_);   // 18 x 32 = 576 CTAs
    conv1_kernel<<<cgrid, 256, smem1>>>(s, x);          // -> bufA
    conv20_kernel<0, 1, 1><<<cgrid, 256, smem20>>>();   // A -> B
    conv20_kernel<1, 0, 2><<<cgrid, 256, smem20>>>();   // B -> A

    dim3 ggrid(NGRP, B_);        // 69 x 16 = 1104 CTAs
    corr_kernel<<<ggrid, 768, smemC>>>(out);
}